// round 3
// baseline (speedup 1.0000x reference)
#include <cuda_runtime.h>

#define EPSF 1e-8f

#define NB 8
#define NH 8
#define NL 4096
#define NK 16
#define ND 256
#define NDH 64
#define NBL (NB*NL)
#define LATS_STRIDE 260

// ---------------- scratch (device globals: no allocation allowed) ----------
__device__ float g_mods[NBL*3];
__device__ float g_stdv[NBL];
__device__ unsigned g_mn[NB];
__device__ unsigned g_mx[NB];

__global__ void init_kernel(){
    int t = threadIdx.x;
    if (t < NB){ g_mn[t] = 0x7F800000u; g_mx[t] = 0u; }
}

// reduce-sum over aligned groups of 8 lanes, result broadcast to the group
__device__ __forceinline__ float red8b(float v){
    v += __shfl_down_sync(0xFFFFFFFFu, v, 4, 8);
    v += __shfl_down_sync(0xFFFFFFFFu, v, 2, 8);
    v += __shfl_down_sync(0xFFFFFFFFu, v, 1, 8);
    return __shfl_sync(0xFFFFFFFFu, v, 0, 8);
}

// reduce-sum over lanes 0..15 (callers guarantee tid<16, warp 0)
__device__ __forceinline__ float red16b(float v){
    v += __shfl_down_sync(0xFFFFu, v, 8, 16);
    v += __shfl_down_sync(0xFFFFu, v, 4, 16);
    v += __shfl_down_sync(0xFFFFu, v, 2, 16);
    v += __shfl_down_sync(0xFFFFu, v, 1, 16);
    return __shfl_sync(0xFFFFu, v, 0, 16);
}

// ---------------- Kernel A: MLP(mods) + feature_std + per-batch min/max ----
__device__ __forceinline__ void finish_row(
    float acc[8], int tx, int row, const float* latrow,
    const float* gs, const float* bs, const float* w2s, const float* b2s)
{
    // exact gelu
    float h[8];
    float s = 0.f, s2 = 0.f;
#pragma unroll
    for (int c = 0; c < 8; c++){
        float x = acc[c];
        float g = 0.5f * x * (1.f + erff(x * 0.70710678118654752f));
        h[c] = g; s += g; s2 += g * g;
    }
    s = red8b(s); s2 = red8b(s2);
    float mu   = s  * (1.f/64.f);
    float var  = s2 * (1.f/64.f) - mu * mu;
    float rstd = rsqrtf(var + 1e-5f);
    float m0 = 0.f, m1 = 0.f, m2 = 0.f;
#pragma unroll
    for (int c = 0; c < 8; c++){
        int j = 8*tx + c;
        float hn = (h[c] - mu) * rstd * gs[j] + bs[j];
        m0 += hn * w2s[j*3+0];
        m1 += hn * w2s[j*3+1];
        m2 += hn * w2s[j*3+2];
    }
    m0 = red8b(m0); m1 = red8b(m1); m2 = red8b(m2);

    // feature_std of the latent row (ddof = 1)
    float ls = 0.f, ls2 = 0.f;
#pragma unroll 8
    for (int i = 0; i < 32; i++){
        float x = latrow[tx*32 + i];
        ls += x; ls2 += x * x;
    }
    ls = red8b(ls); ls2 = red8b(ls2);

    if (tx == 0){
        g_mods[row*3+0] = m0 + b2s[0];
        g_mods[row*3+1] = m1 + b2s[1];
        g_mods[row*3+2] = m2 + b2s[2];
        float mean = ls * (1.f/256.f);
        float v2 = (ls2 - 256.f*mean*mean) * (1.f/255.f);
        float sd = sqrtf(fmaxf(v2, 0.f));
        g_stdv[row] = sd;
        int b = row >> 12;  // row / NL
        atomicMin(&g_mn[b], __float_as_uint(sd));
        atomicMax(&g_mx[b], __float_as_uint(sd));
    }
}

__global__ void __launch_bounds__(256, 1) kernelA(
    const float* __restrict__ lat,  const float* __restrict__ w1,
    const float* __restrict__ b1,   const float* __restrict__ lng,
    const float* __restrict__ lnb,  const float* __restrict__ w2,
    const float* __restrict__ b2)
{
    extern __shared__ float sm[];
    float* w1s  = sm;            // 256*64 = 16384 floats, layout [d*64 + j]
    float* lats = sm + ND*NDH;   // 64 rows * 260 floats (pad kills bank conflicts)
    __shared__ float b1s[NDH], gs[NDH], bs[NDH], w2s[NDH*3], b2s[4];

    int tid = threadIdx.x;

    for (int i = tid; i < (ND*NDH)/4; i += 256)
        ((float4*)w1s)[i] = ((const float4*)w1)[i];
    if (tid < NDH){ b1s[tid] = b1[tid]; gs[tid] = lng[tid]; bs[tid] = lnb[tid]; }
    if (tid < NDH*3) w2s[tid] = w2[tid];
    if (tid < 3)     b2s[tid] = b2[tid];

    int row0 = blockIdx.x * 64;
    for (int i = tid; i < 64*64; i += 256){      // 64 rows x 64 float4
        int r = i >> 6, c = i & 63;
        ((float4*)(lats + r*LATS_STRIDE))[c] =
            ((const float4*)(lat + (size_t)(row0 + r) * ND))[c];
    }
    __syncthreads();

    int tx = tid & 7;        // 8 cols of 8 -> 64 hidden units
    int ty = tid >> 3;       // 32 row-pairs -> 64 rows
    const float* la0 = lats + (2*ty)     * LATS_STRIDE;
    const float* la1 = lats + (2*ty + 1) * LATS_STRIDE;
    int tx8 = 8 * tx;

    float acc0[8], acc1[8];
#pragma unroll
    for (int c = 0; c < 8; c++){ float bb = b1s[tx8 + c]; acc0[c] = bb; acc1[c] = bb; }

#pragma unroll 4
    for (int d = 0; d < ND; d++){
        float a0 = la0[d];
        float a1 = la1[d];
        float4 wA = *(const float4*)(w1s + d*NDH + tx8);
        float4 wB = *(const float4*)(w1s + d*NDH + tx8 + 4);
        acc0[0] = fmaf(a0, wA.x, acc0[0]);  acc1[0] = fmaf(a1, wA.x, acc1[0]);
        acc0[1] = fmaf(a0, wA.y, acc0[1]);  acc1[1] = fmaf(a1, wA.y, acc1[1]);
        acc0[2] = fmaf(a0, wA.z, acc0[2]);  acc1[2] = fmaf(a1, wA.z, acc1[2]);
        acc0[3] = fmaf(a0, wA.w, acc0[3]);  acc1[3] = fmaf(a1, wA.w, acc1[3]);
        acc0[4] = fmaf(a0, wB.x, acc0[4]);  acc1[4] = fmaf(a1, wB.x, acc1[4]);
        acc0[5] = fmaf(a0, wB.y, acc0[5]);  acc1[5] = fmaf(a1, wB.y, acc1[5]);
        acc0[6] = fmaf(a0, wB.z, acc0[6]);  acc1[6] = fmaf(a1, wB.z, acc1[6]);
        acc0[7] = fmaf(a0, wB.w, acc0[7]);  acc1[7] = fmaf(a1, wB.w, acc1[7]);
    }

    finish_row(acc0, tx, row0 + 2*ty,     la0, gs, bs, w2s, b2s);
    finish_row(acc1, tx, row0 + 2*ty + 1, la1, gs, bs, w2s, b2s);
}

// ---------------- Kernel B: the streaming fused pass --------------------
__global__ void __launch_bounds__(128) kernelB(
    const float* __restrict__ lat,   const float* __restrict__ attn,
    const float* __restrict__ nf,    const float* __restrict__ npos,
    const float* __restrict__ cpos,  const float* __restrict__ hw,
    const float* __restrict__ p_temp, const float* __restrict__ p_lba,
    const float* __restrict__ p_lbr,  const float* __restrict__ p_istr,
    float* __restrict__ out)
{
    __shared__ float lats[ND];
    __shared__ float sim[NK], waS[NK], npX[NK], npY[NK], distS[NK];
    __shared__ float hiS[NH];
    __shared__ float red4[4];
    __shared__ float sc_latn, sc_cx, sc_cy;

    int tid  = threadIdx.x;
    int bl   = blockIdx.x;
    int b    = bl >> 12;
    int l    = bl & (NL - 1);
    int warp = tid >> 5, lane = tid & 31;

    // phase 1: latent row into smem + ||lat||
    float2 v = ((const float2*)(lat + (size_t)bl * ND))[tid];
    lats[2*tid]   = v.x;
    lats[2*tid+1] = v.y;
    float sq = v.x*v.x + v.y*v.y;
    sq += __shfl_down_sync(0xFFFFFFFFu, sq, 16);
    sq += __shfl_down_sync(0xFFFFFFFFu, sq, 8);
    sq += __shfl_down_sync(0xFFFFFFFFu, sq, 4);
    sq += __shfl_down_sync(0xFFFFFFFFu, sq, 2);
    sq += __shfl_down_sync(0xFFFFFFFFu, sq, 1);
    if (lane == 0) red4[warp] = sq;
    if (tid < NK) waS[tid] = 0.f;
    if (tid < NH) hiS[tid] = hw[tid];
    __syncthreads();

    if (tid == 0){
        float s = red4[0] + red4[1] + red4[2] + red4[3];
        sc_latn = fmaxf(sqrtf(s), EPSF);
        float2 c = ((const float2*)cpos)[bl];
        sc_cx = c.x; sc_cy = c.y;
        // softmax over head weights
        float hv[NH]; float m = -1e30f;
#pragma unroll
        for (int h = 0; h < NH; h++){ hv[h] = hiS[h]; m = fmaxf(m, hv[h]); }
        float den = 0.f;
#pragma unroll
        for (int h = 0; h < NH; h++){ hv[h] = expf(hv[h] - m); den += hv[h]; }
        float inv = 1.f / den;
#pragma unroll
        for (int h = 0; h < NH; h++) hiS[h] = hv[h] * inv;
    }
    __syncthreads();

    // phase 2: similarity (each warp handles 4 neighbor rows)
    {
        float latn = sc_latn;
        for (int kk = warp*4; kk < warp*4 + 4; kk++){
            const float* nfr = nf + ((size_t)bl * NK + kk) * ND;
            float dot = 0.f, nsq = 0.f;
#pragma unroll
            for (int i = 0; i < 8; i++){
                float x = nfr[lane + 32*i];
                dot += x * lats[lane + 32*i];
                nsq += x * x;
            }
            dot += __shfl_down_sync(0xFFFFFFFFu, dot, 16);
            nsq += __shfl_down_sync(0xFFFFFFFFu, nsq, 16);
            dot += __shfl_down_sync(0xFFFFFFFFu, dot, 8);
            nsq += __shfl_down_sync(0xFFFFFFFFu, nsq, 8);
            dot += __shfl_down_sync(0xFFFFFFFFu, dot, 4);
            nsq += __shfl_down_sync(0xFFFFFFFFu, nsq, 4);
            dot += __shfl_down_sync(0xFFFFFFFFu, dot, 2);
            nsq += __shfl_down_sync(0xFFFFFFFFu, nsq, 2);
            dot += __shfl_down_sync(0xFFFFFFFFu, dot, 1);
            nsq += __shfl_down_sync(0xFFFFFFFFu, nsq, 1);
            if (lane == 0)
                sim[kk] = dot / (latn * fmaxf(sqrtf(nsq), EPSF));
        }
    }

    // phase 3: head-weighted attention (thread = (h,k)), + neighbor positions
    {
        int h  = tid >> 4;
        int kk = tid & 15;
        float val = attn[(((size_t)b * NH + h) * NL + l) * (NK + 1) + 1 + kk] * hiS[h];
        atomicAdd(&waS[kk], val);
    }
    if (tid < NK){
        float2 np = ((const float2*)npos)[(size_t)bl * NK + tid];
        npX[tid] = np.x; npY[tid] = np.y;
        float dx = np.x - sc_cx, dy = np.y - sc_cy;
        distS[tid] = sqrtf(dx*dx + dy*dy);
    }
    __syncthreads();

    // phase 4: finalize (warp 0, lanes 0..15)
    if (tid < NK){
        float wav = waS[tid];
        float ws  = red16b(wav);
        wav = wav / (ws + EPSF);

        float sv   = sim[tid];
        float temp = fabsf(p_temp[0]) + EPSF;
        float rs   = expf(sv / temp) / (distS[tid] + 0.1f);
        float rss  = red16b(rs);
        rs = rs / (rss + EPSF);

        float dx  = npX[tid] - sc_cx;
        float dy  = npY[tid] - sc_cy;
        float inv = 1.f / (distS[tid] + EPSF);

        float wcx = red16b(wav * npX[tid]);
        float wcy = red16b(wav * npY[tid]);
        float rx  = red16b(rs * (-dx * inv));
        float ry  = red16b(rs * (-dy * inv));
        float ssum = red16b(sv);

        if (tid == 0){
            float ax = wcx - sc_cx;
            float ay = wcy - sc_cy;

            float sd = g_stdv[bl];
            float mn = __uint_as_float(g_mn[b]);
            float mx = __uint_as_float(g_mx[b]);
            float complexity = (sd - mn) / (mx - mn + EPSF);
            float uniq = 1.f - ssum * (1.f/16.f);
            float importance = 0.5f * complexity + 0.5f * uniq;
            float istr = 1.f / (1.f + expf(-p_istr[0]));
            float esc  = 1.f - istr * importance;

            float m0 = g_mods[bl*3+0];
            float m1 = g_mods[bl*3+1];
            float m2 = g_mods[bl*3+2];
            float w_at = expf(p_lba[0]) * 2.f / (1.f + expf(-m0));
            float w_rp = expf(p_lbr[0]) * 2.f / (1.f + expf(-m1));
            float fsc  = esc / (1.f + expf(-m2));
            float itw  = 1.f / (w_at + w_rp + EPSF);

            float cxo = (w_at * ax + w_rp * rx) * itw * fsc;
            float cyo = (w_at * ay + w_rp * ry) * itw * fsc;
            out[2*bl]   = tanhf(cxo * 0.2f) * 5.f;
            out[2*bl+1] = tanhf(cyo * 0.2f) * 5.f;
        }
    }
}

// ---------------- launch ------------------------------------------------
extern "C" void kernel_launch(void* const* d_in, const int* in_sizes, int n_in,
                              void* d_out, int out_size)
{
    const float* lat   = (const float*)d_in[0];
    const float* attn  = (const float*)d_in[1];
    const float* nf    = (const float*)d_in[2];
    const float* npos  = (const float*)d_in[3];
    const float* cpos  = (const float*)d_in[4];
    const float* hw    = (const float*)d_in[5];
    const float* p_t   = (const float*)d_in[6];
    const float* p_la  = (const float*)d_in[7];
    const float* p_lr  = (const float*)d_in[8];
    const float* p_is  = (const float*)d_in[9];
    const float* w1    = (const float*)d_in[10];
    const float* b1    = (const float*)d_in[11];
    const float* lng   = (const float*)d_in[12];
    const float* lnb   = (const float*)d_in[13];
    const float* w2    = (const float*)d_in[14];
    const float* b2    = (const float*)d_in[15];
    float* out = (float*)d_out;

    init_kernel<<<1, 32>>>();

    size_t smemA = (size_t)(ND*NDH + 64*LATS_STRIDE) * sizeof(float); // 132 KB
    cudaFuncSetAttribute(kernelA, cudaFuncAttributeMaxDynamicSharedMemorySize, (int)smemA);
    kernelA<<<NBL/64, 256, smemA>>>(lat, w1, b1, lng, lnb, w2, b2);

    kernelB<<<NBL, 128>>>(lat, attn, nf, npos, cpos, hw,
                          p_t, p_la, p_lr, p_is, out);
}

// round 7
// speedup vs baseline: 1.4197x; 1.4197x over previous
#include <cuda_runtime.h>

#define EPSF 1e-8f

#define NB 8
#define NH 8
#define NL 4096
#define NK 16
#define ND 256
#define NDH 64
#define NBL (NB*NL)
#define LATS_STRIDE 260

// ---------------- scratch (device globals: no allocation allowed) ----------
__device__ float g_mods[NBL*3];
__device__ float g_stdv[NBL];
__device__ float g_att[NBL*2];
__device__ unsigned g_mn[NB];
__device__ unsigned g_mx[NB];
__device__ float g_hi[NH];
__device__ float g_scal[4];   // 0: temp, 1: istr, 2: base_attn, 3: base_rep

__global__ void init_kernel(const float* __restrict__ hw,
                            const float* __restrict__ p_t,
                            const float* __restrict__ p_la,
                            const float* __restrict__ p_lr,
                            const float* __restrict__ p_is){
    int t = threadIdx.x;
    if (t < NB){ g_mn[t] = 0x7F800000u; g_mx[t] = 0u; }
    if (t == 0){
        float hv[NH]; float m = -1e30f;
#pragma unroll
        for (int h = 0; h < NH; h++){ hv[h] = hw[h]; m = fmaxf(m, hv[h]); }
        float den = 0.f;
#pragma unroll
        for (int h = 0; h < NH; h++){ hv[h] = expf(hv[h] - m); den += hv[h]; }
        float inv = 1.f / den;
#pragma unroll
        for (int h = 0; h < NH; h++) g_hi[h] = hv[h] * inv;
        g_scal[0] = fabsf(p_t[0]) + EPSF;
        g_scal[1] = 1.f / (1.f + expf(-p_is[0]));
        g_scal[2] = expf(p_la[0]);
        g_scal[3] = expf(p_lr[0]);
    }
}

// reduce-sum over aligned groups of 8 lanes, broadcast to group
__device__ __forceinline__ float red8b(float v){
    v += __shfl_down_sync(0xFFFFFFFFu, v, 4, 8);
    v += __shfl_down_sync(0xFFFFFFFFu, v, 2, 8);
    v += __shfl_down_sync(0xFFFFFFFFu, v, 1, 8);
    return __shfl_sync(0xFFFFFFFFu, v, 0, 8);
}

// reduce-sum over aligned 16-lane halves, all 32 lanes converged (kernelA)
__device__ __forceinline__ float red16_all(float v){
    v += __shfl_down_sync(0xFFFFFFFFu, v, 8, 16);
    v += __shfl_down_sync(0xFFFFFFFFu, v, 4, 16);
    v += __shfl_down_sync(0xFFFFFFFFu, v, 2, 16);
    v += __shfl_down_sync(0xFFFFFFFFu, v, 1, 16);
    return __shfl_sync(0xFFFFFFFFu, v, 0, 16);
}

// reduce-sum over lanes 0..15 only (kernelB finalize, tid<16)
__device__ __forceinline__ float red16_lo(float v){
    v += __shfl_down_sync(0xFFFFu, v, 8, 16);
    v += __shfl_down_sync(0xFFFFu, v, 4, 16);
    v += __shfl_down_sync(0xFFFFu, v, 2, 16);
    v += __shfl_down_sync(0xFFFFu, v, 1, 16);
    return __shfl_sync(0xFFFFu, v, 0, 16);
}

// ---------------- Kernel A: MLP(mods) + std/minmax + attn->attraction -----
__device__ __forceinline__ void finish_row(
    float acc[8], int tx, int row, const float* latrow,
    const float* gs, const float* bs, const float* w2s, const float* b2s)
{
    // exact gelu
    float h[8];
    float s = 0.f, s2 = 0.f;
#pragma unroll
    for (int c = 0; c < 8; c++){
        float x = acc[c];
        float g = 0.5f * x * (1.f + erff(x * 0.70710678118654752f));
        h[c] = g; s += g; s2 += g * g;
    }
    s = red8b(s); s2 = red8b(s2);
    float mu   = s  * (1.f/64.f);
    float var  = s2 * (1.f/64.f) - mu * mu;
    float rstd = rsqrtf(var + 1e-5f);
    float m0 = 0.f, m1 = 0.f, m2 = 0.f;
#pragma unroll
    for (int c = 0; c < 8; c++){
        int j = 8*tx + c;
        float hn = (h[c] - mu) * rstd * gs[j] + bs[j];
        m0 += hn * w2s[j*3+0];
        m1 += hn * w2s[j*3+1];
        m2 += hn * w2s[j*3+2];
    }
    m0 = red8b(m0); m1 = red8b(m1); m2 = red8b(m2);

    // feature_std of the latent row (ddof = 1)
    float ls = 0.f, ls2 = 0.f;
#pragma unroll 8
    for (int i = 0; i < 32; i++){
        float x = latrow[tx*32 + i];
        ls += x; ls2 += x * x;
    }
    ls = red8b(ls); ls2 = red8b(ls2);

    if (tx == 0){
        g_mods[row*3+0] = m0 + b2s[0];
        g_mods[row*3+1] = m1 + b2s[1];
        g_mods[row*3+2] = m2 + b2s[2];
        float mean = ls * (1.f/256.f);
        float v2 = (ls2 - 256.f*mean*mean) * (1.f/255.f);
        float sd = sqrtf(fmaxf(v2, 0.f));
        g_stdv[row] = sd;
        int b = row >> 12;
        atomicMin(&g_mn[b], __float_as_uint(sd));
        atomicMax(&g_mx[b], __float_as_uint(sd));
    }
}

__global__ void __launch_bounds__(256, 1) kernelA(
    const float* __restrict__ lat,  const float* __restrict__ w1,
    const float* __restrict__ b1,   const float* __restrict__ lng,
    const float* __restrict__ lnb,  const float* __restrict__ w2,
    const float* __restrict__ b2,   const float* __restrict__ attn,
    const float* __restrict__ npos, const float* __restrict__ cpos)
{
    extern __shared__ float sm[];
    float* w1s  = sm;            // 256*64 floats, layout [d*64 + j]
    float* lats = sm + ND*NDH;   // 64 rows * 260 floats (padded)
    __shared__ float b1s[NDH], gs[NDH], bs[NDH], w2s[NDH*3], b2s[4];

    int tid = threadIdx.x;
    int row0 = blockIdx.x * 64;

    // stage smem fills (loads in flight while attn phase runs on registers)
    for (int i = tid; i < (ND*NDH)/4; i += 256)
        ((float4*)w1s)[i] = ((const float4*)w1)[i];
    if (tid < NDH){ b1s[tid] = b1[tid]; gs[tid] = lng[tid]; bs[tid] = lnb[tid]; }
    if (tid < NDH*3) w2s[tid] = w2[tid];
    if (tid < 3)     b2s[tid] = b2[tid];
    for (int i = tid; i < 64*64; i += 256){
        int r = i >> 6, c2 = i & 63;
        ((float4*)(lats + r*LATS_STRIDE))[c2] =
            ((const float4*)(lat + (size_t)(row0 + r) * ND))[c2];
    }

    // ---- attention -> attraction (register-only; overlaps smem fill) ----
    {
        float hir[NH];
#pragma unroll
        for (int h = 0; h < NH; h++) hir[h] = g_hi[h];
        int k  = tid & 15;       // neighbor index
        int rp = tid >> 4;       // 0..15 rows per pass
        int bb = row0 >> 12;
        const float* abase = attn + (size_t)bb * NH * NL * (NK + 1);
#pragma unroll
        for (int p = 0; p < 4; p++){
            int row = row0 + p*16 + rp;
            int l   = row & (NL - 1);
            const float* ap = abase + (size_t)l * (NK + 1) + 1 + k;
            float acc = 0.f;
#pragma unroll
            for (int h = 0; h < NH; h++)
                acc += ap[(size_t)h * NL * (NK + 1)] * hir[h];
            float ws = red16_all(acc);
            float wa = acc / (ws + EPSF);
            float2 np = ((const float2*)npos)[(size_t)row * NK + k];
            float wcx = red16_all(wa * np.x);
            float wcy = red16_all(wa * np.y);
            if (k == 0){
                float2 c = ((const float2*)cpos)[row];
                g_att[2*row]   = wcx - c.x;
                g_att[2*row+1] = wcy - c.y;
            }
        }
    }
    __syncthreads();

    // ---- GEMM: 64 rows x (256 -> 64) ----
    int tx = tid & 7;
    int ty = tid >> 3;
    const float* la0 = lats + (2*ty)     * LATS_STRIDE;
    const float* la1 = lats + (2*ty + 1) * LATS_STRIDE;
    int tx8 = 8 * tx;

    float acc0[8], acc1[8];
#pragma unroll
    for (int c = 0; c < 8; c++){ float bb2 = b1s[tx8 + c]; acc0[c] = bb2; acc1[c] = bb2; }

#pragma unroll 4
    for (int d = 0; d < ND; d++){
        float a0 = la0[d];
        float a1 = la1[d];
        float4 wA = *(const float4*)(w1s + d*NDH + tx8);
        float4 wB = *(const float4*)(w1s + d*NDH + tx8 + 4);
        acc0[0] = fmaf(a0, wA.x, acc0[0]);  acc1[0] = fmaf(a1, wA.x, acc1[0]);
        acc0[1] = fmaf(a0, wA.y, acc0[1]);  acc1[1] = fmaf(a1, wA.y, acc1[1]);
        acc0[2] = fmaf(a0, wA.z, acc0[2]);  acc1[2] = fmaf(a1, wA.z, acc1[2]);
        acc0[3] = fmaf(a0, wA.w, acc0[3]);  acc1[3] = fmaf(a1, wA.w, acc1[3]);
        acc0[4] = fmaf(a0, wB.x, acc0[4]);  acc1[4] = fmaf(a1, wB.x, acc1[4]);
        acc0[5] = fmaf(a0, wB.y, acc0[5]);  acc1[5] = fmaf(a1, wB.y, acc1[5]);
        acc0[6] = fmaf(a0, wB.z, acc0[6]);  acc1[6] = fmaf(a1, wB.z, acc1[6]);
        acc0[7] = fmaf(a0, wB.w, acc0[7]);  acc1[7] = fmaf(a1, wB.w, acc1[7]);
    }

    finish_row(acc0, tx, row0 + 2*ty,     la0, gs, bs, w2s, b2s);
    finish_row(acc1, tx, row0 + 2*ty + 1, la1, gs, bs, w2s, b2s);
}

// ---------------- Kernel B: pure streaming similarity + finalize ---------
__global__ void __launch_bounds__(128) kernelB(
    const float* __restrict__ lat,  const float* __restrict__ nf,
    const float* __restrict__ npos, const float* __restrict__ cpos,
    float* __restrict__ out)
{
    __shared__ float4 latS[64];
    __shared__ float simS[NK], dxS[NK], dyS[NK], distS[NK];
    __shared__ float red4w[4];

    int tid  = threadIdx.x;
    int bl   = blockIdx.x;
    int b    = bl >> 12;
    int warp = tid >> 5, lane = tid & 31;

    // latent row (64 float4 by threads 0..63) + ||lat||^2 partials
    float sq = 0.f;
    if (tid < 64){
        float4 v = ((const float4*)(lat + (size_t)bl * ND))[tid];
        latS[tid] = v;
        sq = v.x*v.x + v.y*v.y + v.z*v.z + v.w*v.w;
    }
    // npos + delta/dist (independent; issued early)
    if (tid < NK){
        float2 np = ((const float2*)npos)[(size_t)bl * NK + tid];
        float2 c  = ((const float2*)cpos)[bl];
        float dx = np.x - c.x, dy = np.y - c.y;
        dxS[tid] = dx; dyS[tid] = dy;
        distS[tid] = sqrtf(dx*dx + dy*dy);
    }
    sq += __shfl_down_sync(0xFFFFFFFFu, sq, 16);
    sq += __shfl_down_sync(0xFFFFFFFFu, sq, 8);
    sq += __shfl_down_sync(0xFFFFFFFFu, sq, 4);
    sq += __shfl_down_sync(0xFFFFFFFFu, sq, 2);
    sq += __shfl_down_sync(0xFFFFFFFFu, sq, 1);
    if (lane == 0) red4w[warp] = sq;
    __syncthreads();

    float latn = fmaxf(sqrtf(red4w[0] + red4w[1] + red4w[2] + red4w[3]), EPSF);

    // similarity: lane -> (row-within-4, chunk-of-8-float4); 8 independent LDG.128
    {
        int r = lane >> 3, c = lane & 7;
        int row = (warp << 2) + r;
        const float4* nfr = (const float4*)(nf + ((size_t)bl * NK + row) * ND);
        float dot = 0.f, nsq = 0.f;
#pragma unroll
        for (int j = 0; j < 8; j++){
            float4 a  = nfr[c + 8*j];
            float4 lv = latS[c + 8*j];
            dot += a.x*lv.x + a.y*lv.y + a.z*lv.z + a.w*lv.w;
            nsq += a.x*a.x + a.y*a.y + a.z*a.z + a.w*a.w;
        }
        dot += __shfl_down_sync(0xFFFFFFFFu, dot, 4, 8);
        nsq += __shfl_down_sync(0xFFFFFFFFu, nsq, 4, 8);
        dot += __shfl_down_sync(0xFFFFFFFFu, dot, 2, 8);
        nsq += __shfl_down_sync(0xFFFFFFFFu, nsq, 2, 8);
        dot += __shfl_down_sync(0xFFFFFFFFu, dot, 1, 8);
        nsq += __shfl_down_sync(0xFFFFFFFFu, nsq, 1, 8);
        if (c == 0)
            simS[row] = dot / (latn * fmaxf(sqrtf(nsq), EPSF));
    }
    __syncthreads();

    // finalize (warp 0, lanes 0..15)
    if (tid < NK){
        float sv   = simS[tid];
        float ssum = red16_lo(sv);

        float rs  = expf(sv / g_scal[0]) / (distS[tid] + 0.1f);
        float rss = red16_lo(rs);
        rs = rs / (rss + EPSF);

        float inv = 1.f / (distS[tid] + EPSF);
        float rx  = red16_lo(rs * (-dxS[tid] * inv));
        float ry  = red16_lo(rs * (-dyS[tid] * inv));

        if (tid == 0){
            float ax = g_att[2*bl], ay = g_att[2*bl+1];

            float sd = g_stdv[bl];
            float mn = __uint_as_float(g_mn[b]);
            float mx = __uint_as_float(g_mx[b]);
            float complexity = (sd - mn) / (mx - mn + EPSF);
            float uniq = 1.f - ssum * (1.f/16.f);
            float importance = 0.5f * complexity + 0.5f * uniq;
            float esc = 1.f - g_scal[1] * importance;

            float m0 = g_mods[3*bl+0];
            float m1 = g_mods[3*bl+1];
            float m2 = g_mods[3*bl+2];
            float w_at = g_scal[2] * 2.f / (1.f + expf(-m0));
            float w_rp = g_scal[3] * 2.f / (1.f + expf(-m1));
            float fsc  = esc / (1.f + expf(-m2));
            float itw  = 1.f / (w_at + w_rp + EPSF);

            float cx = (w_at * ax + w_rp * rx) * itw * fsc;
            float cy = (w_at * ay + w_rp * ry) * itw * fsc;
            out[2*bl]   = tanhf(cx * 0.2f) * 5.f;
            out[2*bl+1] = tanhf(cy * 0.2f) * 5.f;
        }
    }
}

// ---------------- launch ------------------------------------------------
extern "C" void kernel_launch(void* const* d_in, const int* in_sizes, int n_in,
                              void* d_out, int out_size)
{
    const float* lat   = (const float*)d_in[0];
    const float* attn  = (const float*)d_in[1];
    const float* nf    = (const float*)d_in[2];
    const float* npos  = (const float*)d_in[3];
    const float* cpos  = (const float*)d_in[4];
    const float* hw    = (const float*)d_in[5];
    const float* p_t   = (const float*)d_in[6];
    const float* p_la  = (const float*)d_in[7];
    const float* p_lr  = (const float*)d_in[8];
    const float* p_is  = (const float*)d_in[9];
    const float* w1    = (const float*)d_in[10];
    const float* b1    = (const float*)d_in[11];
    const float* lng   = (const float*)d_in[12];
    const float* lnb   = (const float*)d_in[13];
    const float* w2    = (const float*)d_in[14];
    const float* b2    = (const float*)d_in[15];
    float* out = (float*)d_out;

    init_kernel<<<1, 32>>>(hw, p_t, p_la, p_lr, p_is);

    size_t smemA = (size_t)(ND*NDH + 64*LATS_STRIDE) * sizeof(float); // 132 KB
    cudaFuncSetAttribute(kernelA, cudaFuncAttributeMaxDynamicSharedMemorySize, (int)smemA);
    kernelA<<<NBL/64, 256, smemA>>>(lat, w1, b1, lng, lnb, w2, b2,
                                    attn, npos, cpos);

    kernelB<<<NBL, 128>>>(lat, nf, npos, cpos, out);
}

// round 9
// speedup vs baseline: 2.0242x; 1.4257x over previous
#include <cuda_runtime.h>

#define EPSF 1e-8f

#define NB 8
#define NH 8
#define NL 4096
#define NK 16
#define ND 256
#define NDH 64
#define NBL (NB*NL)
#define NABLK 512            // A-blocks (64 rows each)
#define NBBLK (NBL/2)        // B-blocks (2 rows each)

// ---------------- scratch (device globals) -------------------------------
__device__ float  g_mods[NBL*3];
__device__ float  g_stdv[NBL];
__device__ float2 g_att[NBL];
__device__ float4 g_rep[NBL];

// reduce-sum over aligned groups of 8 lanes, broadcast to group
__device__ __forceinline__ float red8b(float v){
    v += __shfl_down_sync(0xFFFFFFFFu, v, 4, 8);
    v += __shfl_down_sync(0xFFFFFFFFu, v, 2, 8);
    v += __shfl_down_sync(0xFFFFFFFFu, v, 1, 8);
    return __shfl_sync(0xFFFFFFFFu, v, 0, 8);
}
// reduce-sum over aligned 16-lane halves, all lanes converged
__device__ __forceinline__ float red16_all(float v){
    v += __shfl_down_sync(0xFFFFFFFFu, v, 8, 16);
    v += __shfl_down_sync(0xFFFFFFFFu, v, 4, 16);
    v += __shfl_down_sync(0xFFFFFFFFu, v, 2, 16);
    v += __shfl_down_sync(0xFFFFFFFFu, v, 1, 16);
    return __shfl_sync(0xFFFFFFFFu, v, 0, 16);
}
// reduce-sum over lanes 0..15 only (guarded callers)
__device__ __forceinline__ float red16_lo(float v){
    v += __shfl_down_sync(0xFFFFu, v, 8, 16);
    v += __shfl_down_sync(0xFFFFu, v, 4, 16);
    v += __shfl_down_sync(0xFFFFu, v, 2, 16);
    v += __shfl_down_sync(0xFFFFu, v, 1, 16);
    return __shfl_sync(0xFFFFu, v, 0, 16);
}

// ---------------- A path: MLP(mods) + feature_std + attn->attraction ------
__device__ __forceinline__ void finish_row(
    float acc[8], int tx, int row, const float* __restrict__ latrow,
    const float* __restrict__ lng, const float* __restrict__ lnb,
    const float* __restrict__ w2,  const float* __restrict__ b2)
{
    // exact gelu
    float h[8];
    float s = 0.f, s2 = 0.f;
#pragma unroll
    for (int c = 0; c < 8; c++){
        float x = acc[c];
        float g = 0.5f * x * (1.f + erff(x * 0.70710678118654752f));
        h[c] = g; s += g; s2 += g * g;
    }
    s = red8b(s); s2 = red8b(s2);
    float mu   = s  * (1.f/64.f);
    float var  = s2 * (1.f/64.f) - mu * mu;
    float rstd = rsqrtf(var + 1e-5f);
    float m0 = 0.f, m1 = 0.f, m2 = 0.f;
#pragma unroll
    for (int c = 0; c < 8; c++){
        int j = 8*tx + c;
        float hn = (h[c] - mu) * rstd * lng[j] + lnb[j];
        m0 += hn * w2[j*3+0];
        m1 += hn * w2[j*3+1];
        m2 += hn * w2[j*3+2];
    }
    m0 = red8b(m0); m1 = red8b(m1); m2 = red8b(m2);

    // feature_std of the latent row (ddof = 1)
    float ls = 0.f, ls2 = 0.f;
    const float4* lr4 = (const float4*)(latrow) + tx*8;
#pragma unroll
    for (int i = 0; i < 8; i++){
        float4 v = lr4[i];
        ls  += v.x + v.y + v.z + v.w;
        ls2 += v.x*v.x + v.y*v.y + v.z*v.z + v.w*v.w;
    }
    ls = red8b(ls); ls2 = red8b(ls2);

    if (tx == 0){
        g_mods[row*3+0] = m0 + b2[0];
        g_mods[row*3+1] = m1 + b2[1];
        g_mods[row*3+2] = m2 + b2[2];
        float mean = ls * (1.f/256.f);
        float v2 = (ls2 - 256.f*mean*mean) * (1.f/255.f);
        g_stdv[row] = sqrtf(fmaxf(v2, 0.f));
    }
}

__device__ __forceinline__ void a_path(
    int ablk, int tid,
    const float* __restrict__ lat,  const float* __restrict__ w1,
    const float* __restrict__ b1,   const float* __restrict__ lng,
    const float* __restrict__ lnb,  const float* __restrict__ w2,
    const float* __restrict__ b2,   const float* __restrict__ attn,
    const float* __restrict__ npos, const float* __restrict__ cpos,
    const float* __restrict__ hw)
{
    int row0 = ablk * 64;

    // ---- attention -> attraction (register-only) ----
    {
        float hir[NH];
        {
            float m = -1e30f;
#pragma unroll
            for (int h = 0; h < NH; h++){ hir[h] = hw[h]; m = fmaxf(m, hir[h]); }
            float den = 0.f;
#pragma unroll
            for (int h = 0; h < NH; h++){ hir[h] = expf(hir[h] - m); den += hir[h]; }
            float inv = 1.f / den;
#pragma unroll
            for (int h = 0; h < NH; h++) hir[h] *= inv;
        }
        int k  = tid & 15;
        int rp = tid >> 4;
        int bb = row0 >> 12;
        const float* abase = attn + (size_t)bb * NH * NL * (NK + 1);
#pragma unroll
        for (int p = 0; p < 4; p++){
            int row = row0 + p*16 + rp;
            int l   = row & (NL - 1);
            const float* ap = abase + (size_t)l * (NK + 1) + 1 + k;
            float acc = 0.f;
#pragma unroll
            for (int h = 0; h < NH; h++)
                acc += ap[(size_t)h * NL * (NK + 1)] * hir[h];
            float ws = red16_all(acc);
            float wa = acc / (ws + EPSF);
            float2 np = ((const float2*)npos)[(size_t)row * NK + k];
            float wcx = red16_all(wa * np.x);
            float wcy = red16_all(wa * np.y);
            if (k == 0){
                float2 c = ((const float2*)cpos)[row];
                g_att[row] = make_float2(wcx - c.x, wcy - c.y);
            }
        }
    }

    // ---- GEMM: 64 rows x (256 -> 64), w1 + latents via L1 ----
    int tx = tid & 7;
    int ty = tid >> 3;
    int tx8 = 8 * tx;
    const float*  la0 = lat + (size_t)(row0 + 2*ty) * ND;
    const float*  la1 = la0 + ND;
    const float4* A0p = (const float4*)la0;
    const float4* A1p = (const float4*)la1;

    float acc0[8], acc1[8];
#pragma unroll
    for (int c = 0; c < 8; c++){ float bb2 = b1[tx8 + c]; acc0[c] = bb2; acc1[c] = bb2; }

    for (int d4 = 0; d4 < 64; d4++){
        float4 A0 = A0p[d4];
        float4 A1 = A1p[d4];
        float a0s[4] = {A0.x, A0.y, A0.z, A0.w};
        float a1s[4] = {A1.x, A1.y, A1.z, A1.w};
#pragma unroll
        for (int q = 0; q < 4; q++){
            const float* wr = w1 + (size_t)(4*d4 + q) * NDH + tx8;
            float4 wA = *(const float4*)(wr);
            float4 wB = *(const float4*)(wr + 4);
            float a0 = a0s[q], a1 = a1s[q];
            acc0[0] = fmaf(a0, wA.x, acc0[0]);  acc1[0] = fmaf(a1, wA.x, acc1[0]);
            acc0[1] = fmaf(a0, wA.y, acc0[1]);  acc1[1] = fmaf(a1, wA.y, acc1[1]);
            acc0[2] = fmaf(a0, wA.z, acc0[2]);  acc1[2] = fmaf(a1, wA.z, acc1[2]);
            acc0[3] = fmaf(a0, wA.w, acc0[3]);  acc1[3] = fmaf(a1, wA.w, acc1[3]);
            acc0[4] = fmaf(a0, wB.x, acc0[4]);  acc1[4] = fmaf(a1, wB.x, acc1[4]);
            acc0[5] = fmaf(a0, wB.y, acc0[5]);  acc1[5] = fmaf(a1, wB.y, acc1[5]);
            acc0[6] = fmaf(a0, wB.z, acc0[6]);  acc1[6] = fmaf(a1, wB.z, acc1[6]);
            acc0[7] = fmaf(a0, wB.w, acc0[7]);  acc1[7] = fmaf(a1, wB.w, acc1[7]);
        }
    }

    finish_row(acc0, tx, row0 + 2*ty,     la0, lng, lnb, w2, b2);
    finish_row(acc1, tx, row0 + 2*ty + 1, la1, lng, lnb, w2, b2);
}

// ---------------- B path: streaming similarity + repulsion ----------------
__device__ __forceinline__ void b_path(
    int bblk, int tid,
    const float* __restrict__ lat,  const float* __restrict__ nf,
    const float* __restrict__ npos, const float* __restrict__ cpos,
    const float* __restrict__ p_t)
{
    __shared__ float4 latS[2][64];
    __shared__ float  dxS[2][NK], dyS[2][NK], distS[2][NK], simS[2][NK];
    __shared__ float  redw[2][4];

    int half  = tid >> 7;          // 0/1 : which of the two rows
    int t     = tid & 127;
    int bl    = bblk * 2 + half;
    int warp4 = (tid >> 5) & 3;
    int lane  = tid & 31;

    float sq = 0.f;
    if (t < 64){
        float4 v = ((const float4*)(lat + (size_t)bl * ND))[t];
        latS[half][t] = v;
        sq = v.x*v.x + v.y*v.y + v.z*v.z + v.w*v.w;
    }
    if (t < NK){
        float2 np = ((const float2*)npos)[(size_t)bl * NK + t];
        float2 c  = ((const float2*)cpos)[bl];
        float dx = np.x - c.x, dy = np.y - c.y;
        dxS[half][t] = dx; dyS[half][t] = dy;
        distS[half][t] = sqrtf(dx*dx + dy*dy);
    }
    sq += __shfl_down_sync(0xFFFFFFFFu, sq, 16);
    sq += __shfl_down_sync(0xFFFFFFFFu, sq, 8);
    sq += __shfl_down_sync(0xFFFFFFFFu, sq, 4);
    sq += __shfl_down_sync(0xFFFFFFFFu, sq, 2);
    sq += __shfl_down_sync(0xFFFFFFFFu, sq, 1);
    if (lane == 0) redw[half][warp4] = sq;
    __syncthreads();

    float latn = fmaxf(sqrtf(redw[half][0] + redw[half][1] +
                             redw[half][2] + redw[half][3]), EPSF);

    // similarity: warp handles 4 neighbor rows; 8 independent LDG.128/thread
    {
        int r = lane >> 3, c = lane & 7;
        int row = warp4 * 4 + r;
        const float4* nfr = (const float4*)(nf + ((size_t)bl * NK + row) * ND);
        float dot = 0.f, nsq = 0.f;
#pragma unroll
        for (int j = 0; j < 8; j++){
            float4 a  = nfr[c + 8*j];
            float4 lv = latS[half][c + 8*j];
            dot += a.x*lv.x + a.y*lv.y + a.z*lv.z + a.w*lv.w;
            nsq += a.x*a.x + a.y*a.y + a.z*a.z + a.w*a.w;
        }
        dot += __shfl_down_sync(0xFFFFFFFFu, dot, 4, 8);
        nsq += __shfl_down_sync(0xFFFFFFFFu, nsq, 4, 8);
        dot += __shfl_down_sync(0xFFFFFFFFu, dot, 2, 8);
        nsq += __shfl_down_sync(0xFFFFFFFFu, nsq, 2, 8);
        dot += __shfl_down_sync(0xFFFFFFFFu, dot, 1, 8);
        nsq += __shfl_down_sync(0xFFFFFFFFu, nsq, 1, 8);
        if (c == 0)
            simS[half][row] = dot / (latn * fmaxf(sqrtf(nsq), EPSF));
    }
    __syncthreads();

    // repulsion reduction (warp 0 of each half, lanes 0..15)
    if (warp4 == 0 && lane < NK){
        int k = lane;
        float sv   = simS[half][k];
        float ssum = red16_lo(sv);

        float temp = fabsf(p_t[0]) + EPSF;
        float rs  = expf(sv / temp) / (distS[half][k] + 0.1f);
        float rss = red16_lo(rs);
        rs = rs / (rss + EPSF);

        float inv = 1.f / (distS[half][k] + EPSF);
        float rx  = red16_lo(rs * (-dxS[half][k] * inv));
        float ry  = red16_lo(rs * (-dyS[half][k] * inv));

        if (k == 0)
            g_rep[bl] = make_float4(rx, ry, ssum, 0.f);
    }
}

__global__ void __launch_bounds__(256, 4) fat_kernel(
    const float* __restrict__ lat,  const float* __restrict__ w1,
    const float* __restrict__ b1,   const float* __restrict__ lng,
    const float* __restrict__ lnb,  const float* __restrict__ w2,
    const float* __restrict__ b2,   const float* __restrict__ attn,
    const float* __restrict__ npos, const float* __restrict__ cpos,
    const float* __restrict__ hw,   const float* __restrict__ nf,
    const float* __restrict__ p_t)
{
    int blk = blockIdx.x;
    if (blk < NABLK)
        a_path(blk, threadIdx.x, lat, w1, b1, lng, lnb, w2, b2,
               attn, npos, cpos, hw);
    else
        b_path(blk - NABLK, threadIdx.x, lat, nf, npos, cpos, p_t);
}

// ---------------- Kernel C: per-batch min/max + finalize ------------------
__global__ void __launch_bounds__(1024) kernelC(
    const float* __restrict__ p_la, const float* __restrict__ p_lr,
    const float* __restrict__ p_is, float* __restrict__ out)
{
    __shared__ float s_mn[32], s_mx[32];
    int b   = blockIdx.x;           // 0..7
    int tid = threadIdx.x;          // 0..1023
    int lane = tid & 31, warp = tid >> 5;

    float mn =  1e30f, mx = -1e30f;
#pragma unroll
    for (int i = 0; i < NL/1024; i++){
        float sd = g_stdv[b*NL + tid + i*1024];
        mn = fminf(mn, sd); mx = fmaxf(mx, sd);
    }
#pragma unroll
    for (int o = 16; o; o >>= 1){
        mn = fminf(mn, __shfl_down_sync(0xFFFFFFFFu, mn, o));
        mx = fmaxf(mx, __shfl_down_sync(0xFFFFFFFFu, mx, o));
    }
    if (lane == 0){ s_mn[warp] = mn; s_mx[warp] = mx; }
    __syncthreads();
    if (tid < 32){
        mn = s_mn[tid]; mx = s_mx[tid];
#pragma unroll
        for (int o = 16; o; o >>= 1){
            mn = fminf(mn, __shfl_down_sync(0xFFFFFFFFu, mn, o));
            mx = fmaxf(mx, __shfl_down_sync(0xFFFFFFFFu, mx, o));
        }
        if (tid == 0){ s_mn[0] = mn; s_mx[0] = mx; }
    }
    __syncthreads();
    float mnv = s_mn[0], mxv = s_mx[0];

    float istr = 1.f / (1.f + expf(-p_is[0]));
    float ba   = expf(p_la[0]);
    float br   = expf(p_lr[0]);

#pragma unroll
    for (int i = 0; i < NL/1024; i++){
        int bl = b*NL + tid + i*1024;
        float4 rep = g_rep[bl];
        float2 at  = g_att[bl];
        float  sd  = g_stdv[bl];

        float complexity = (sd - mnv) / (mxv - mnv + EPSF);
        float uniq = 1.f - rep.z * (1.f/16.f);
        float importance = 0.5f * complexity + 0.5f * uniq;
        float esc = 1.f - istr * importance;

        float m0 = g_mods[3*bl+0];
        float m1 = g_mods[3*bl+1];
        float m2 = g_mods[3*bl+2];
        float w_at = ba * 2.f / (1.f + expf(-m0));
        float w_rp = br * 2.f / (1.f + expf(-m1));
        float fsc  = esc / (1.f + expf(-m2));
        float itw  = 1.f / (w_at + w_rp + EPSF);

        float cx = (w_at * at.x + w_rp * rep.x) * itw * fsc;
        float cy = (w_at * at.y + w_rp * rep.y) * itw * fsc;
        ((float2*)out)[bl] = make_float2(tanhf(cx * 0.2f) * 5.f,
                                         tanhf(cy * 0.2f) * 5.f);
    }
}

// ---------------- launch --------------------------------------------------
extern "C" void kernel_launch(void* const* d_in, const int* in_sizes, int n_in,
                              void* d_out, int out_size)
{
    const float* lat   = (const float*)d_in[0];
    const float* attn  = (const float*)d_in[1];
    const float* nf    = (const float*)d_in[2];
    const float* npos  = (const float*)d_in[3];
    const float* cpos  = (const float*)d_in[4];
    const float* hw    = (const float*)d_in[5];
    const float* p_t   = (const float*)d_in[6];
    const float* p_la  = (const float*)d_in[7];
    const float* p_lr  = (const float*)d_in[8];
    const float* p_is  = (const float*)d_in[9];
    const float* w1    = (const float*)d_in[10];
    const float* b1    = (const float*)d_in[11];
    const float* lng   = (const float*)d_in[12];
    const float* lnb   = (const float*)d_in[13];
    const float* w2    = (const float*)d_in[14];
    const float* b2    = (const float*)d_in[15];
    float* out = (float*)d_out;

    fat_kernel<<<NABLK + NBBLK, 256>>>(lat, w1, b1, lng, lnb, w2, b2,
                                       attn, npos, cpos, hw, nf, p_t);
    kernelC<<<NB, 1024>>>(p_la, p_lr, p_is, out);
}

// round 12
// speedup vs baseline: 2.0621x; 1.0188x over previous
#include <cuda_runtime.h>

#define EPSF 1e-8f

#define NB 8
#define NH 8
#define NL 4096
#define NK 16
#define ND 256
#define NDH 64
#define NBL (NB*NL)
#define NABLK 512            // A-blocks (64 rows each)
#define NBBLK (NBL/2)        // B-blocks (2 rows each)

typedef unsigned long long u64;

// ---------------- scratch (device globals) -------------------------------
__device__ float  g_mods[NBL*3];
__device__ float  g_stdv[NBL];
__device__ float2 g_att[NBL];
__device__ float4 g_rep[NBL];

// ---------------- packed f32x2 helpers -----------------------------------
__device__ __forceinline__ u64 pack2(float lo, float hi){
    u64 r; asm("mov.b64 %0, {%1, %2};" : "=l"(r) : "f"(lo), "f"(hi)); return r;
}
__device__ __forceinline__ void unpack2(u64 v, float& lo, float& hi){
    asm("mov.b64 {%0, %1}, %2;" : "=f"(lo), "=f"(hi) : "l"(v));
}
__device__ __forceinline__ u64 ffma2(u64 a, u64 b, u64 c){
    u64 d; asm("fma.rn.f32x2 %0, %1, %2, %3;" : "=l"(d) : "l"(a), "l"(b), "l"(c));
    return d;
}

// ---------------- reductions ----------------------------------------------
__device__ __forceinline__ float red8b(float v){
    v += __shfl_down_sync(0xFFFFFFFFu, v, 4, 8);
    v += __shfl_down_sync(0xFFFFFFFFu, v, 2, 8);
    v += __shfl_down_sync(0xFFFFFFFFu, v, 1, 8);
    return __shfl_sync(0xFFFFFFFFu, v, 0, 8);
}
__device__ __forceinline__ float red16_all(float v){
    v += __shfl_down_sync(0xFFFFFFFFu, v, 8, 16);
    v += __shfl_down_sync(0xFFFFFFFFu, v, 4, 16);
    v += __shfl_down_sync(0xFFFFFFFFu, v, 2, 16);
    v += __shfl_down_sync(0xFFFFFFFFu, v, 1, 16);
    return __shfl_sync(0xFFFFFFFFu, v, 0, 16);
}
__device__ __forceinline__ float red16_lo(float v){
    v += __shfl_down_sync(0xFFFFu, v, 8, 16);
    v += __shfl_down_sync(0xFFFFu, v, 4, 16);
    v += __shfl_down_sync(0xFFFFu, v, 2, 16);
    v += __shfl_down_sync(0xFFFFu, v, 1, 16);
    return __shfl_sync(0xFFFFu, v, 0, 16);
}

// ---------------- A path: MLP(mods) + feature_std + attn->attraction ------
__device__ __forceinline__ void finish_row(
    float acc[8], int tx, int row, const float* __restrict__ latrow,
    const float* __restrict__ lng, const float* __restrict__ lnb,
    const float* __restrict__ w2,  const float* __restrict__ b2)
{
    float h[8];
    float s = 0.f, s2 = 0.f;
#pragma unroll
    for (int c = 0; c < 8; c++){
        float x = acc[c];
        float g = 0.5f * x * (1.f + erff(x * 0.70710678118654752f));
        h[c] = g; s += g; s2 += g * g;
    }
    s = red8b(s); s2 = red8b(s2);
    float mu   = s  * (1.f/64.f);
    float var  = s2 * (1.f/64.f) - mu * mu;
    float rstd = rsqrtf(var + 1e-5f);
    float m0 = 0.f, m1 = 0.f, m2 = 0.f;
#pragma unroll
    for (int c = 0; c < 8; c++){
        int j = 8*tx + c;
        float hn = (h[c] - mu) * rstd * lng[j] + lnb[j];
        m0 += hn * w2[j*3+0];
        m1 += hn * w2[j*3+1];
        m2 += hn * w2[j*3+2];
    }
    m0 = red8b(m0); m1 = red8b(m1); m2 = red8b(m2);

    float ls = 0.f, ls2 = 0.f;
    const float4* lr4 = (const float4*)(latrow) + tx*8;
#pragma unroll
    for (int i = 0; i < 8; i++){
        float4 v = lr4[i];
        ls  += v.x + v.y + v.z + v.w;
        ls2 += v.x*v.x + v.y*v.y + v.z*v.z + v.w*v.w;
    }
    ls = red8b(ls); ls2 = red8b(ls2);

    if (tx == 0){
        g_mods[row*3+0] = m0 + b2[0];
        g_mods[row*3+1] = m1 + b2[1];
        g_mods[row*3+2] = m2 + b2[2];
        float mean = ls * (1.f/256.f);
        float v2 = (ls2 - 256.f*mean*mean) * (1.f/255.f);
        g_stdv[row] = sqrtf(fmaxf(v2, 0.f));
    }
}

__device__ __forceinline__ void a_path(
    int ablk, int tid,
    const float* __restrict__ lat,  const float* __restrict__ w1,
    const float* __restrict__ b1,   const float* __restrict__ lng,
    const float* __restrict__ lnb,  const float* __restrict__ w2,
    const float* __restrict__ b2,   const float* __restrict__ attn,
    const float* __restrict__ npos, const float* __restrict__ cpos,
    const float* __restrict__ hw)
{
    int row0 = ablk * 64;

    // attention -> attraction (register-only)
    {
        float hir[NH];
        {
            float m = -1e30f;
#pragma unroll
            for (int h = 0; h < NH; h++){ hir[h] = hw[h]; m = fmaxf(m, hir[h]); }
            float den = 0.f;
#pragma unroll
            for (int h = 0; h < NH; h++){ hir[h] = expf(hir[h] - m); den += hir[h]; }
            float inv = 1.f / den;
#pragma unroll
            for (int h = 0; h < NH; h++) hir[h] *= inv;
        }
        int k  = tid & 15;
        int rp = tid >> 4;
        int bb = row0 >> 12;
        const float* abase = attn + (size_t)bb * NH * NL * (NK + 1);
#pragma unroll
        for (int p = 0; p < 4; p++){
            int row = row0 + p*16 + rp;
            int l   = row & (NL - 1);
            const float* ap = abase + (size_t)l * (NK + 1) + 1 + k;
            float acc = 0.f;
#pragma unroll
            for (int h = 0; h < NH; h++)
                acc += ap[(size_t)h * NL * (NK + 1)] * hir[h];
            float ws = red16_all(acc);
            float wa = acc / (ws + EPSF);
            float2 np = ((const float2*)npos)[(size_t)row * NK + k];
            float wcx = red16_all(wa * np.x);
            float wcy = red16_all(wa * np.y);
            if (k == 0){
                float2 c = ((const float2*)cpos)[row];
                g_att[row] = make_float2(wcx - c.x, wcy - c.y);
            }
        }
    }

    // GEMM: 64 rows x (256 -> 64), packed f32x2
    int tx = tid & 7;
    int ty = tid >> 3;
    int tx8 = 8 * tx;
    const float*  la0 = lat + (size_t)(row0 + 2*ty) * ND;
    const float*  la1 = la0 + ND;
    const float4* A0p = (const float4*)la0;
    const float4* A1p = (const float4*)la1;

    u64 accP0[4], accP1[4];
#pragma unroll
    for (int c2 = 0; c2 < 4; c2++){
        u64 bb2 = pack2(b1[tx8 + 2*c2], b1[tx8 + 2*c2 + 1]);
        accP0[c2] = bb2; accP1[c2] = bb2;
    }

    for (int d4 = 0; d4 < 64; d4++){
        float4 A0 = A0p[d4];
        float4 A1 = A1p[d4];
        float a0s[4] = {A0.x, A0.y, A0.z, A0.w};
        float a1s[4] = {A1.x, A1.y, A1.z, A1.w};
#pragma unroll
        for (int q = 0; q < 4; q++){
            const ulonglong2* wr =
                (const ulonglong2*)(w1 + (size_t)(4*d4 + q) * NDH + tx8);
            ulonglong2 wa = wr[0];
            ulonglong2 wb = wr[1];
            u64 a0d = pack2(a0s[q], a0s[q]);
            u64 a1d = pack2(a1s[q], a1s[q]);
            accP0[0] = ffma2(a0d, wa.x, accP0[0]);
            accP1[0] = ffma2(a1d, wa.x, accP1[0]);
            accP0[1] = ffma2(a0d, wa.y, accP0[1]);
            accP1[1] = ffma2(a1d, wa.y, accP1[1]);
            accP0[2] = ffma2(a0d, wb.x, accP0[2]);
            accP1[2] = ffma2(a1d, wb.x, accP1[2]);
            accP0[3] = ffma2(a0d, wb.y, accP0[3]);
            accP1[3] = ffma2(a1d, wb.y, accP1[3]);
        }
    }

    float acc0[8], acc1[8];
#pragma unroll
    for (int c2 = 0; c2 < 4; c2++){
        unpack2(accP0[c2], acc0[2*c2], acc0[2*c2+1]);
        unpack2(accP1[c2], acc1[2*c2], acc1[2*c2+1]);
    }

    finish_row(acc0, tx, row0 + 2*ty,     la0, lng, lnb, w2, b2);
    finish_row(acc1, tx, row0 + 2*ty + 1, la1, lng, lnb, w2, b2);
}

// ---------------- B path: warp-self-contained streaming -------------------
__device__ __forceinline__ void b_path(
    int bblk, int tid,
    const float* __restrict__ lat,  const float* __restrict__ nf,
    const float* __restrict__ npos, const float* __restrict__ cpos,
    const float* __restrict__ p_t)
{
    __shared__ float simS[2][NK];

    int w    = tid >> 5;
    int half = w >> 2;
    int q    = w & 3;
    int lane = tid & 31;
    int r    = lane >> 3;
    int c    = lane & 7;
    int bl   = bblk * 2 + half;
    int k    = q * 4 + r;

    const float4* lat4 = (const float4*)(lat + (size_t)bl * ND);
    const float4* nfr  = (const float4*)(nf + ((size_t)bl * NK + k) * ND);

    float dot = 0.f, nsq = 0.f, lsq = 0.f;
#pragma unroll
    for (int j = 0; j < 8; j++){
        float4 a  = nfr[c + 8*j];
        float4 lv = lat4[c + 8*j];
        dot += a.x*lv.x + a.y*lv.y + a.z*lv.z + a.w*lv.w;
        nsq += a.x*a.x + a.y*a.y + a.z*a.z + a.w*a.w;
        lsq += lv.x*lv.x + lv.y*lv.y + lv.z*lv.z + lv.w*lv.w;
    }
    dot = red8b(dot); nsq = red8b(nsq); lsq = red8b(lsq);
    if (c == 0){
        float latn = fmaxf(sqrtf(lsq), EPSF);
        simS[half][k] = dot / (latn * fmaxf(sqrtf(nsq), EPSF));
    }
    __syncthreads();

    if (q == 0 && lane < NK){
        int kk = lane;
        float2 np = ((const float2*)npos)[(size_t)bl * NK + kk];
        float2 cp = ((const float2*)cpos)[bl];
        float dx = np.x - cp.x, dy = np.y - cp.y;
        float dist = sqrtf(dx*dx + dy*dy);

        float sv   = simS[half][kk];
        float ssum = red16_lo(sv);

        float temp = fabsf(p_t[0]) + EPSF;
        float rs  = expf(sv / temp) / (dist + 0.1f);
        float rss = red16_lo(rs);
        rs = rs / (rss + EPSF);

        float inv = 1.f / (dist + EPSF);
        float rx  = red16_lo(rs * (-dx * inv));
        float ry  = red16_lo(rs * (-dy * inv));

        if (kk == 0)
            g_rep[bl] = make_float4(rx, ry, ssum, 0.f);
    }
}

__global__ void __launch_bounds__(256, 4) fat_kernel(
    const float* __restrict__ lat,  const float* __restrict__ w1,
    const float* __restrict__ b1,   const float* __restrict__ lng,
    const float* __restrict__ lnb,  const float* __restrict__ w2,
    const float* __restrict__ b2,   const float* __restrict__ attn,
    const float* __restrict__ npos, const float* __restrict__ cpos,
    const float* __restrict__ hw,   const float* __restrict__ nf,
    const float* __restrict__ p_t)
{
    int blk = blockIdx.x;
    if (blk < NABLK)
        a_path(blk, threadIdx.x, lat, w1, b1, lng, lnb, w2, b2,
               attn, npos, cpos, hw);
    else
        b_path(blk - NABLK, threadIdx.x, lat, nf, npos, cpos, p_t);
}

// ---------------- Kernel C: 64 blocks (batch, seg) ------------------------
__global__ void __launch_bounds__(512) kernelC(
    const float* __restrict__ p_la, const float* __restrict__ p_lr,
    const float* __restrict__ p_is, float* __restrict__ out)
{
    __shared__ float s_mn[16], s_mx[16];
    int batch = blockIdx.x >> 3;
    int seg   = blockIdx.x & 7;
    int tid   = threadIdx.x;
    int lane = tid & 31, warp = tid >> 5;

    float mn =  1e30f, mx = -1e30f;
#pragma unroll
    for (int i = 0; i < NL/512; i++){
        float sd = g_stdv[batch*NL + tid + i*512];
        mn = fminf(mn, sd); mx = fmaxf(mx, sd);
    }
#pragma unroll
    for (int o = 16; o; o >>= 1){
        mn = fminf(mn, __shfl_down_sync(0xFFFFFFFFu, mn, o));
        mx = fmaxf(mx, __shfl_down_sync(0xFFFFFFFFu, mx, o));
    }
    if (lane == 0){ s_mn[warp] = mn; s_mx[warp] = mx; }
    __syncthreads();
    if (tid < 16){
        mn = s_mn[tid]; mx = s_mx[tid];
#pragma unroll
        for (int o = 8; o; o >>= 1){
            mn = fminf(mn, __shfl_down_sync(0xFFFFu, mn, o));
            mx = fmaxf(mx, __shfl_down_sync(0xFFFFu, mx, o));
        }
        if (tid == 0){ s_mn[0] = mn; s_mx[0] = mx; }
    }
    __syncthreads();
    float mnv = s_mn[0], mxv = s_mx[0];

    float istr = 1.f / (1.f + expf(-p_is[0]));
    float ba   = expf(p_la[0]);
    float br   = expf(p_lr[0]);

    int bl = batch*NL + seg*512 + tid;
    float4 rep = g_rep[bl];
    float2 at  = g_att[bl];
    float  sd  = g_stdv[bl];

    float complexity = (sd - mnv) / (mxv - mnv + EPSF);
    float uniq = 1.f - rep.z * (1.f/16.f);
    float importance = 0.5f * complexity + 0.5f * uniq;
    float esc = 1.f - istr * importance;

    float m0 = g_mods[3*bl+0];
    float m1 = g_mods[3*bl+1];
    float m2 = g_mods[3*bl+2];
    float w_at = ba * 2.f / (1.f + expf(-m0));
    float w_rp = br * 2.f / (1.f + expf(-m1));
    float fsc  = esc / (1.f + expf(-m2));
    float itw  = 1.f / (w_at + w_rp + EPSF);

    float cx = (w_at * at.x + w_rp * rep.x) * itw * fsc;
    float cy = (w_at * at.y + w_rp * rep.y) * itw * fsc;
    ((float2*)out)[bl] = make_float2(tanhf(cx * 0.2f) * 5.f,
                                     tanhf(cy * 0.2f) * 5.f);
}

// ---------------- launch --------------------------------------------------
extern "C" void kernel_launch(void* const* d_in, const int* in_sizes, int n_in,
                              void* d_out, int out_size)
{
    const float* lat   = (const float*)d_in[0];
    const float* attn  = (const float*)d_in[1];
    const float* nf    = (const float*)d_in[2];
    const float* npos  = (const float*)d_in[3];
    const float* cpos  = (const float*)d_in[4];
    const float* hw    = (const float*)d_in[5];
    const float* p_t   = (const float*)d_in[6];
    const float* p_la  = (const float*)d_in[7];
    const float* p_lr  = (const float*)d_in[8];
    const float* p_is  = (const float*)d_in[9];
    const float* w1    = (const float*)d_in[10];
    const float* b1    = (const float*)d_in[11];
    const float* lng   = (const float*)d_in[12];
    const float* lnb   = (const float*)d_in[13];
    const float* w2    = (const float*)d_in[14];
    const float* b2    = (const float*)d_in[15];
    float* out = (float*)d_out;

    fat_kernel<<<NABLK + NBBLK, 256>>>(lat, w1, b1, lng, lnb, w2, b2,
                                       attn, npos, cpos, hw, nf, p_t);
    kernelC<<<64, 512>>>(p_la, p_lr, p_is, out);
}